// round 16
// baseline (speedup 1.0000x reference)
#include <cuda_runtime.h>
#include <cuda_bf16.h>
#include <cuda_fp8.h>
#include <math.h>
#include <stdint.h>

#define BATCH 32
#define DIMQ  64
#define NPROM 4
#define DD    1024
#define EE    768
#define VCV   32000
#define MM    (BATCH*DIMQ)   // 2048
#define TOPK  2
#define NCAND 16
#define NSEL  (MM * TOPK)    // 4096
#define EPSV  1e-8f

// -------- scratch --------
__device__ unsigned char  g_scores8[(size_t)MM * VCV];   // e4m3 approx scores
__device__ __nv_bfloat16  g_sh[(size_t)MM * DD];
__device__ __nv_bfloat16  g_sl[(size_t)MM * DD];
__device__ __nv_bfloat16  g_fwh[(size_t)VCV * EE];
__device__ __nv_bfloat16  g_fwl[(size_t)VCV * EE];
__device__ __nv_bfloat16  g_weh[(size_t)DD * EE];
__device__ __nv_bfloat16  g_wel[(size_t)DD * EE];
__device__ __nv_bfloat16  g_weTh[(size_t)EE * DD];
__device__ __nv_bfloat16  g_weTl[(size_t)EE * DD];
__device__ __nv_bfloat16  g_ub[(size_t)MM * EE];     // bf16 u for scores MMA
__device__ float          g_uf[(size_t)MM * EE];     // fp32 u for exact rescore
__device__ __nv_bfloat16  g_Gh[(size_t)EE * EE];     // bf16(we^T we)
__device__ float g_wsump[32 * EE];
__device__ float g_qp[6 * VCV];
__device__ float g_wp[6 * VCV];
__device__ float g_wn[VCV];
__device__ float g_invwn[VCV];
__device__ float g_pn[MM];
__device__ float g_S[MM];
__device__ int   g_candi[MM * NCAND];
__device__ float g_topv[MM * TOPK];
__device__ int   g_topi[MM * TOPK];

// ---------------- helpers ----------------
__device__ __forceinline__ void cp_async16(void* smem, const void* gmem)
{
    uint32_t s = (uint32_t)__cvta_generic_to_shared(smem);
    asm volatile("cp.async.cg.shared.global [%0], [%1], 16;\n" :: "r"(s), "l"(gmem));
}
__device__ __forceinline__ void cp_commit()
{
    asm volatile("cp.async.commit_group;\n" ::);
}
template<int N>
__device__ __forceinline__ void cp_wait()
{
    asm volatile("cp.async.wait_group %0;\n" :: "n"(N));
}

__device__ __forceinline__ void mma16816(float d[4], const uint32_t a[4], const uint32_t b[2])
{
    asm volatile(
        "mma.sync.aligned.m16n8k16.row.col.f32.bf16.bf16.f32 "
        "{%0,%1,%2,%3}, {%4,%5,%6,%7}, {%8,%9}, {%0,%1,%2,%3};"
        : "+f"(d[0]), "+f"(d[1]), "+f"(d[2]), "+f"(d[3])
        : "r"(a[0]), "r"(a[1]), "r"(a[2]), "r"(a[3]), "r"(b[0]), "r"(b[1]));
}

__device__ __forceinline__ void ldsm_x4(uint32_t& r0, uint32_t& r1, uint32_t& r2, uint32_t& r3,
                                        uint32_t addr)
{
    asm volatile("ldmatrix.sync.aligned.m8n8.x4.shared.b16 {%0,%1,%2,%3}, [%4];"
                 : "=r"(r0), "=r"(r1), "=r"(r2), "=r"(r3) : "r"(addr));
}

// 8 floats per thread (used only for fe_w now)
__global__ __launch_bounds__(256) void split_kernel(const float* __restrict__ in,
                                                    __nv_bfloat16* __restrict__ hi,
                                                    __nv_bfloat16* __restrict__ lo,
                                                    int n8)
{
    int i = blockIdx.x * 256 + threadIdx.x;
    if (i >= n8) return;
    #pragma unroll
    for (int q = 0; q < 2; q++) {
        int j = i * 2 + q;
        float4 x = ((const float4*)in)[j];
        __nv_bfloat16 h0 = __float2bfloat16(x.x);
        __nv_bfloat16 h1 = __float2bfloat16(x.y);
        __nv_bfloat16 h2 = __float2bfloat16(x.z);
        __nv_bfloat16 h3 = __float2bfloat16(x.w);
        __nv_bfloat162 hp0{h0, h1}, hp1{h2, h3};
        uint2 hv{*(uint32_t*)&hp0, *(uint32_t*)&hp1};
        ((uint2*)hi)[j] = hv;
        __nv_bfloat162 lp0{__float2bfloat16(x.x - __bfloat162float(h0)),
                           __float2bfloat16(x.y - __bfloat162float(h1))};
        __nv_bfloat162 lp1{__float2bfloat16(x.z - __bfloat162float(h2)),
                           __float2bfloat16(x.w - __bfloat162float(h3))};
        uint2 lv{*(uint32_t*)&lp0, *(uint32_t*)&lp1};
        ((uint2*)lo)[j] = lv;
    }
}

// Fused: we -> weh/wel (row-major split), weTh/weTl (transposed split),
//        wsum partials per 32-row d-block
__global__ void trans_split_kernel(const float* __restrict__ we)
{
    __shared__ float tile[32][33];
    __shared__ float colsum[8][32];
    const int e0 = blockIdx.x * 32;
    const int d0 = blockIdx.y * 32;
    const int tx = threadIdx.x;
    const int ty = threadIdx.y;
    float csum = 0.f;
    #pragma unroll
    for (int i = 0; i < 32; i += 8) {
        float x = we[(size_t)(d0 + ty + i) * EE + e0 + tx];
        tile[ty + i][tx] = x;
        csum += x;
        __nv_bfloat16 h = __float2bfloat16(x);
        size_t ro = (size_t)(d0 + ty + i) * EE + e0 + tx;
        g_weh[ro] = h;
        g_wel[ro] = __float2bfloat16(x - __bfloat162float(h));
    }
    colsum[ty][tx] = csum;
    __syncthreads();
    #pragma unroll
    for (int i = 0; i < 32; i += 8) {
        float x = tile[tx][ty + i];
        size_t o = (size_t)(e0 + ty + i) * DD + d0 + tx;
        __nv_bfloat16 h = __float2bfloat16(x);
        g_weTh[o] = h;
        g_weTl[o] = __float2bfloat16(x - __bfloat162float(h));
    }
    if (ty == 0) {
        float s = 0.f;
        #pragma unroll
        for (int j = 0; j < 8; j++) s += colsum[j][tx];
        g_wsump[(size_t)blockIdx.y * EE + e0 + tx] = s;
    }
}

// ---- MMA tile geometry: 128x128x32, 3-stage pipeline ----
#define BKT     32
#define PADT    8
#define LDST    (BKT + PADT)
#define NSTG    3
#define TILE_ST (128 * LDST)
#define SMEM_BYTES (NSTG * 2 * TILE_ST * 2)   // 61440 B

#define MMA_PREAMBLE \
    extern __shared__ __nv_bfloat16 smem[]; \
    __nv_bfloat16* Asm = smem; \
    __nv_bfloat16* Bsm = smem + NSTG * TILE_ST; \
    const int tid    = threadIdx.x; \
    const int lane   = tid & 31; \
    const int warp   = tid >> 5; \
    const int warp_m = warp >> 2; \
    const int warp_n = warp & 3; \
    const int gid    = lane >> 2; \
    const int tig    = lane & 3; \
    const int c0 = tid * 2, c1 = tid * 2 + 1; \
    const int r0 = c0 >> 2, s0 = (c0 & 3) * 8; \
    const int r1 = c1 >> 2, s1 = (c1 & 3) * 8; \
    const int aRow = warp_m * 64 + (lane & 15); \
    const int aCol = (lane >> 4) * 8; \
    const int bRow = warp_n * 32 + (lane & 7) + ((lane >> 4) << 3); \
    const int bCol = ((lane >> 3) & 1) * 8; \
    const uint32_t sA = (uint32_t)__cvta_generic_to_shared(Asm); \
    const uint32_t sB = (uint32_t)__cvta_generic_to_shared(Bsm); \
    const uint32_t aBase = sA + (uint32_t)(aRow * LDST + aCol) * 2; \
    const uint32_t bBase = sB + (uint32_t)(bRow * LDST + bCol) * 2; \
    float acc[4][4][4]; \
    _Pragma("unroll") \
    for (int mi = 0; mi < 4; mi++) \
        _Pragma("unroll") \
        for (int nj = 0; nj < 4; nj++) \
            _Pragma("unroll") \
            for (int q = 0; q < 4; q++) acc[mi][nj][q] = 0.f;

#define MMA_COMPUTE_TILE(stage) \
    { \
        const uint32_t aB = aBase + (uint32_t)((stage) * TILE_ST) * 2; \
        const uint32_t bB = bBase + (uint32_t)((stage) * TILE_ST) * 2; \
        _Pragma("unroll") \
        for (int ks = 0; ks < 2; ks++) { \
            const uint32_t kOff = (uint32_t)(ks * 16) * 2; \
            uint32_t a[4][4]; \
            uint32_t b[4][2]; \
            _Pragma("unroll") \
            for (int mi = 0; mi < 4; mi++) \
                ldsm_x4(a[mi][0], a[mi][1], a[mi][2], a[mi][3], \
                        aB + (uint32_t)(mi * 16 * LDST) * 2 + kOff); \
            _Pragma("unroll") \
            for (int njp = 0; njp < 2; njp++) \
                ldsm_x4(b[njp*2][0], b[njp*2][1], b[njp*2+1][0], b[njp*2+1][1], \
                        bB + (uint32_t)(njp * 16 * LDST) * 2 + kOff); \
            _Pragma("unroll") \
            for (int mi = 0; mi < 4; mi++) \
                _Pragma("unroll") \
                for (int nj = 0; nj < 4; nj++) \
                    mma16816(acc[mi][nj], a[mi], b[nj]); \
        } \
    }

#define MMA_MAINLOOP(NT, LOADT) \
    LOADT(0, 0); \
    LOADT(1, 1); \
    for (int t = 0; t < (NT); t++) { \
        if (t + 2 < (NT)) { cp_wait<1>(); } else { cp_wait<0>(); } \
        __syncthreads(); \
        if (t + 2 < (NT)) LOADT(t + 2, (t + 2) % NSTG); \
        MMA_COMPUTE_TILE(t % NSTG) \
    }

// =================================================================
// u GEMM: u[m,e] = sum_d s[m,d]*we[d,e] (3-pass split) -> ub bf16 + uf fp32
// =================================================================
__global__ __launch_bounds__(256, 2) void mma_u_kernel()
{
    MMA_PREAMBLE
    const int m0 = blockIdx.y * 128;
    const int n0 = blockIdx.x * 128;

    const int NT = 96;
    auto load_tile = [&](int t, int stage) {
        const int pass = t / 32;
        const int kk   = (t % 32) * BKT;
        const __nv_bfloat16* Ap = (pass < 2) ? g_sh : g_sl;
        const __nv_bfloat16* Bp = (pass == 1) ? g_weTl : g_weTh;
        cp_async16(Asm + stage * TILE_ST + r0 * LDST + s0, Ap + (size_t)(m0 + r0) * DD + kk + s0);
        cp_async16(Asm + stage * TILE_ST + r1 * LDST + s1, Ap + (size_t)(m0 + r1) * DD + kk + s1);
        cp_async16(Bsm + stage * TILE_ST + r0 * LDST + s0, Bp + (size_t)(n0 + r0) * DD + kk + s0);
        cp_async16(Bsm + stage * TILE_ST + r1 * LDST + s1, Bp + (size_t)(n0 + r1) * DD + kk + s1);
        cp_commit();
    };

    MMA_MAINLOOP(NT, load_tile)

    #pragma unroll
    for (int mi = 0; mi < 4; mi++) {
        const int gm0 = m0 + warp_m * 64 + mi * 16 + gid;
        #pragma unroll
        for (int nj = 0; nj < 4; nj++) {
            const int gn = n0 + warp_n * 32 + nj * 8 + tig * 2;
            __nv_bfloat16* o0 = g_ub + (size_t)gm0 * EE + gn;
            __nv_bfloat16* o1 = g_ub + (size_t)(gm0 + 8) * EE + gn;
            o0[0] = __float2bfloat16(acc[mi][nj][0]);
            o0[1] = __float2bfloat16(acc[mi][nj][1]);
            o1[0] = __float2bfloat16(acc[mi][nj][2]);
            o1[1] = __float2bfloat16(acc[mi][nj][3]);
            float* f0 = g_uf + (size_t)gm0 * EE + gn;
            float* f1 = g_uf + (size_t)(gm0 + 8) * EE + gn;
            f0[0] = acc[mi][nj][0];  f0[1] = acc[mi][nj][1];
            f1[0] = acc[mi][nj][2];  f1[1] = acc[mi][nj][3];
        }
    }
}

// =================================================================
// G GEMM: G = we^T we (3-pass split) -> Gh bf16
// =================================================================
__global__ __launch_bounds__(256, 2) void mma_G_kernel()
{
    MMA_PREAMBLE
    const int m0 = blockIdx.y * 128;
    const int n0 = blockIdx.x * 128;

    const int NT = 96;
    auto load_tile = [&](int t, int stage) {
        const int pass = t / 32;
        const int kk   = (t % 32) * BKT;
        const __nv_bfloat16* Ap = (pass < 2) ? g_weTh : g_weTl;
        const __nv_bfloat16* Bp = (pass == 1) ? g_weTl : g_weTh;
        cp_async16(Asm + stage * TILE_ST + r0 * LDST + s0, Ap + (size_t)(m0 + r0) * DD + kk + s0);
        cp_async16(Asm + stage * TILE_ST + r1 * LDST + s1, Ap + (size_t)(m0 + r1) * DD + kk + s1);
        cp_async16(Bsm + stage * TILE_ST + r0 * LDST + s0, Bp + (size_t)(n0 + r0) * DD + kk + s0);
        cp_async16(Bsm + stage * TILE_ST + r1 * LDST + s1, Bp + (size_t)(n0 + r1) * DD + kk + s1);
        cp_commit();
    };

    MMA_MAINLOOP(NT, load_tile)

    #pragma unroll
    for (int mi = 0; mi < 4; mi++) {
        const int gm0 = m0 + warp_m * 64 + mi * 16 + gid;
        #pragma unroll
        for (int nj = 0; nj < 4; nj++) {
            const int gn = n0 + warp_n * 32 + nj * 8 + tig * 2;
            g_Gh[(size_t)gm0 * EE + gn]       = __float2bfloat16(acc[mi][nj][0]);
            g_Gh[(size_t)gm0 * EE + gn + 1]   = __float2bfloat16(acc[mi][nj][1]);
            g_Gh[(size_t)(gm0+8) * EE + gn]   = __float2bfloat16(acc[mi][nj][2]);
            g_Gh[(size_t)(gm0+8) * EE + gn+1] = __float2bfloat16(acc[mi][nj][3]);
        }
    }
}

// =================================================================
// H GEMM (1-pass) + fused q/w partials
// =================================================================
__global__ __launch_bounds__(256, 2) void mma_H_kernel()
{
    MMA_PREAMBLE
    const int m0 = blockIdx.y * 128;   // v
    const int n0 = blockIdx.x * 128;   // e

    const int NT = EE / BKT;  // 24
    auto load_tile = [&](int t, int stage) {
        const int kk = t * BKT;
        cp_async16(Asm + stage * TILE_ST + r0 * LDST + s0, g_fwh + (size_t)(m0 + r0) * EE + kk + s0);
        cp_async16(Asm + stage * TILE_ST + r1 * LDST + s1, g_fwh + (size_t)(m0 + r1) * EE + kk + s1);
        cp_async16(Bsm + stage * TILE_ST + r0 * LDST + s0, g_Gh + (size_t)(n0 + r0) * EE + kk + s0);
        cp_async16(Bsm + stage * TILE_ST + r1 * LDST + s1, g_Gh + (size_t)(n0 + r1) * EE + kk + s1);
        cp_commit();
    };

    MMA_MAINLOOP(NT, load_tile)

    __syncthreads();
    float* rowq = (float*)smem;
    float* roww = (float*)smem + 128;
    float* wsm  = (float*)smem + 256;
    if (tid < 128) { rowq[tid] = 0.f; roww[tid] = 0.f; }
    if (tid < 128) {
        float s = 0.f;
        #pragma unroll
        for (int i = 0; i < 32; i++)
            s += g_wsump[(size_t)i * EE + n0 + tid];
        wsm[tid] = s;
    }
    __syncthreads();

    #pragma unroll
    for (int mi = 0; mi < 4; mi++) {
        const int lr0 = warp_m * 64 + mi * 16 + gid;
        const int gm0 = m0 + lr0;
        float q0 = 0.f, q1 = 0.f, w0 = 0.f, w1 = 0.f;
        #pragma unroll
        for (int nj = 0; nj < 4; nj++) {
            const int gn = n0 + warp_n * 32 + nj * 8 + tig * 2;
            const int ln = gn - n0;
            __nv_bfloat162 h0 = *(const __nv_bfloat162*)(g_fwh + (size_t)gm0 * EE + gn);
            __nv_bfloat162 l0 = *(const __nv_bfloat162*)(g_fwl + (size_t)gm0 * EE + gn);
            __nv_bfloat162 h1 = *(const __nv_bfloat162*)(g_fwh + (size_t)(gm0+8) * EE + gn);
            __nv_bfloat162 l1 = *(const __nv_bfloat162*)(g_fwl + (size_t)(gm0+8) * EE + gn);
            float fh00 = __bfloat162float(h0.x), fh01 = __bfloat162float(h0.y);
            float fl00 = __bfloat162float(l0.x), fl01 = __bfloat162float(l0.y);
            float fh10 = __bfloat162float(h1.x), fh11 = __bfloat162float(h1.y);
            float fl10 = __bfloat162float(l1.x), fl11 = __bfloat162float(l1.y);
            q0 += acc[mi][nj][0] * (fh00 + 2.f * fl00) + acc[mi][nj][1] * (fh01 + 2.f * fl01);
            q1 += acc[mi][nj][2] * (fh10 + 2.f * fl10) + acc[mi][nj][3] * (fh11 + 2.f * fl11);
            w0 += (fh00 + fl00) * wsm[ln] + (fh01 + fl01) * wsm[ln + 1];
            w1 += (fh10 + fl10) * wsm[ln] + (fh11 + fl11) * wsm[ln + 1];
        }
        atomicAdd(&rowq[lr0], q0);
        atomicAdd(&rowq[lr0 + 8], q1);
        atomicAdd(&roww[lr0], w0);
        atomicAdd(&roww[lr0 + 8], w1);
    }
    __syncthreads();
    if (tid < 128) {
        g_qp[(size_t)blockIdx.x * VCV + m0 + tid] = rowq[tid];
        g_wp[(size_t)blockIdx.x * VCV + m0 + tid] = roww[tid];
    }
}

__global__ __launch_bounds__(256) void wnorm_fin_kernel(const float* __restrict__ fe_b)
{
    const int v = blockIdx.x * 256 + threadIdx.x;
    float q = 0.f, w = 0.f;
    #pragma unroll
    for (int i = 0; i < 6; i++) {
        q += g_qp[(size_t)i * VCV + v];
        w += g_wp[(size_t)i * VCV + v];
    }
    const float b = fe_b[v];
    float nsq = fmaxf(q + 2.f * b * w + (float)DD * b * b, 0.f);
    float wn = fmaxf(2.0f * sqrtf(nsq), EPSV);
    g_wn[v] = wn;
    g_invwn[v] = 1.0f / wn;
}

// =================================================================
// scores[m,v] = (ub[m].fwh[v] + b[v]*S[m]) * invwn[v], stored e4m3
// =================================================================
__global__ __launch_bounds__(256, 2) void mma_scores_kernel(const float* __restrict__ fe_b)
{
    MMA_PREAMBLE
    const int m0 = blockIdx.y * 128;
    const int n0 = blockIdx.x * 128;

    const int NT = EE / BKT;  // 24
    auto load_tile = [&](int t, int stage) {
        const int kk = t * BKT;
        cp_async16(Asm + stage * TILE_ST + r0 * LDST + s0, g_ub + (size_t)(m0 + r0) * EE + kk + s0);
        cp_async16(Asm + stage * TILE_ST + r1 * LDST + s1, g_ub + (size_t)(m0 + r1) * EE + kk + s1);
        cp_async16(Bsm + stage * TILE_ST + r0 * LDST + s0, g_fwh + (size_t)(n0 + r0) * EE + kk + s0);
        cp_async16(Bsm + stage * TILE_ST + r1 * LDST + s1, g_fwh + (size_t)(n0 + r1) * EE + kk + s1);
        cp_commit();
    };

    MMA_MAINLOOP(NT, load_tile)

    #pragma unroll
    for (int mi = 0; mi < 4; mi++) {
        const int gm0 = m0 + warp_m * 64 + mi * 16 + gid;
        const float S0 = g_S[gm0];
        const float S1 = g_S[gm0 + 8];
        #pragma unroll
        for (int nj = 0; nj < 4; nj++) {
            const int gn = n0 + warp_n * 32 + nj * 8 + tig * 2;
            const float iw0 = g_invwn[gn],  iw1 = g_invwn[gn + 1];
            const float bb0 = fe_b[gn],     bb1 = fe_b[gn + 1];
            float2 v0 = make_float2((acc[mi][nj][0] + bb0 * S0) * iw0,
                                    (acc[mi][nj][1] + bb1 * S0) * iw1);
            float2 v1 = make_float2((acc[mi][nj][2] + bb0 * S1) * iw0,
                                    (acc[mi][nj][3] + bb1 * S1) * iw1);
            *(unsigned short*)(g_scores8 + (size_t)gm0 * VCV + gn) =
                __nv_cvt_float2_to_fp8x2(v0, __NV_SATFINITE, __NV_E4M3);
            *(unsigned short*)(g_scores8 + (size_t)(gm0 + 8) * VCV + gn) =
                __nv_cvt_float2_to_fp8x2(v1, __NV_SATFINITE, __NV_E4M3);
        }
    }
}

// =================================================================
// Tsel GEMM: Z e_k rows (gathered, 3-pass split, writes into out)
// =================================================================
__global__ __launch_bounds__(256, 2) void mma_Tsel_kernel(const float* __restrict__ fe_b,
                                                          float* __restrict__ out)
{
    MMA_PREAMBLE
    const int m0 = blockIdx.y * 128;
    const int n0 = blockIdx.x * 128;

    const int sel0 = g_topi[m0 + r0];
    const int sel1 = g_topi[m0 + r1];

    const int NT = 72;
    auto load_tile = [&](int t, int stage) {
        const int pass = t / 24;
        const int kk   = (t % 24) * BKT;
        const __nv_bfloat16* Ap = (pass < 2) ? g_fwh : g_fwl;
        const __nv_bfloat16* Bp = (pass == 1) ? g_wel : g_weh;
        cp_async16(Asm + stage * TILE_ST + r0 * LDST + s0, Ap + (size_t)sel0 * EE + kk + s0);
        cp_async16(Asm + stage * TILE_ST + r1 * LDST + s1, Ap + (size_t)sel1 * EE + kk + s1);
        cp_async16(Bsm + stage * TILE_ST + r0 * LDST + s0, Bp + (size_t)(n0 + r0) * EE + kk + s0);
        cp_async16(Bsm + stage * TILE_ST + r1 * LDST + s1, Bp + (size_t)(n0 + r1) * EE + kk + s1);
        cp_commit();
    };

    MMA_MAINLOOP(NT, load_tile)

    #pragma unroll
    for (int mi = 0; mi < 4; mi++) {
        const int gm0 = m0 + warp_m * 64 + mi * 16 + gid;
        const int gm1 = gm0 + 8;
        const float b0 = fe_b[g_topi[gm0]];
        const float b1 = fe_b[g_topi[gm1]];
        float* dst0 = out + ((size_t)(gm0 >> 1) * (NPROM + TOPK) + (gm0 & 1)) * DD;
        float* dst1 = out + ((size_t)(gm1 >> 1) * (NPROM + TOPK) + (gm1 & 1)) * DD;
        #pragma unroll
        for (int nj = 0; nj < 4; nj++) {
            const int gn = n0 + warp_n * 32 + nj * 8 + tig * 2;
            dst0[gn]     = acc[mi][nj][0] + b0;
            dst0[gn + 1] = acc[mi][nj][1] + b0;
            dst1[gn]     = acc[mi][nj][2] + b1;
            dst1[gn + 1] = acc[mi][nj][3] + b1;
        }
    }
}

// ---------------- small kernels ----------------
__global__ __launch_bounds__(256) void s_pnorm_kernel(const float* __restrict__ P)
{
    const int m = blockIdx.x;
    const float* base = P + (size_t)m * NPROM * DD;
    float ss = 0.f, rs = 0.f;
    #pragma unroll
    for (int i = 0; i < 4; i++) {
        int d = threadIdx.x + i * 256;
        float a = base[d];
        float b = base[DD + d];
        float c = base[2 * DD + d];
        float e = base[3 * DD + d];
        float sum = (a + b) + (c + e);
        __nv_bfloat16 h = __float2bfloat16(sum);
        g_sh[(size_t)m * DD + d] = h;
        g_sl[(size_t)m * DD + d] = __float2bfloat16(sum - __bfloat162float(h));
        ss += a * a + b * b + c * c + e * e;
        rs += sum;
    }
    __shared__ float red[256];
    __shared__ float red2[256];
    red[threadIdx.x] = ss;
    red2[threadIdx.x] = rs;
    __syncthreads();
    for (int o = 128; o > 0; o >>= 1) {
        if (threadIdx.x < o) {
            red[threadIdx.x]  += red[threadIdx.x + o];
            red2[threadIdx.x] += red2[threadIdx.x + o];
        }
        __syncthreads();
    }
    if (threadIdx.x == 0) {
        g_pn[m] = fmaxf(sqrtf(red[0]), EPSV);
        g_S[m]  = red2[0];
    }
}

// ordered e4m3 byte -> monotone u8 (satfinite: no NaN present)
__device__ __forceinline__ uint32_t ord_fp8(uint32_t b)
{
    return (b & 0x80u) ? (~b & 0xFFu) : (b | 0x80u);
}

// top-16 per row, e4m3 scores, u32 keys (ord8<<15 | (32767-idx))
__global__ __launch_bounds__(256) void top16_kernel()
{
    const int m   = blockIdx.x;
    const int tid = threadIdx.x;
    const int lane = tid & 31, warp = tid >> 5;
    const uint4* row = (const uint4*)(g_scores8 + (size_t)m * VCV);

    uint32_t loc[4] = {0u, 0u, 0u, 0u};

    for (int i = tid; i < VCV / 16; i += 256) {
        uint4 x = row[i];
        const int base = i * 16;
        uint32_t ws[4] = {x.x, x.y, x.z, x.w};
        #pragma unroll
        for (int p = 0; p < 4; p++) {
            #pragma unroll
            for (int h = 0; h < 4; h++) {
                uint32_t bits = (ws[p] >> (h * 8)) & 0xFFu;
                int idx = base + p * 4 + h;
                uint32_t key = (ord_fp8(bits) << 15) | (uint32_t)(32767 - idx);
                if (key > loc[3]) {
                    bool placed = false;
                    #pragma unroll
                    for (int j = 3; j >= 1; --j) {
                        if (!placed) {
                            if (key > loc[j - 1]) loc[j] = loc[j - 1];
                            else { loc[j] = key; placed = true; }
                        }
                    }
                    if (!placed) loc[0] = key;
                }
            }
        }
    }

    __shared__ uint32_t pool[1024];
    __shared__ uint32_t wk[8];
    __shared__ int      wp[8];
    #pragma unroll
    for (int j = 0; j < 4; j++) pool[tid * 4 + j] = loc[j];
    __syncthreads();

    for (int r = 0; r < NCAND; r++) {
        uint32_t best = pool[tid * 4];
        int bp = tid * 4;
        #pragma unroll
        for (int j = 1; j < 4; j++) {
            uint32_t k = pool[tid * 4 + j];
            if (k > best) { best = k; bp = tid * 4 + j; }
        }
        #pragma unroll
        for (int o = 16; o > 0; o >>= 1) {
            uint32_t ok = __shfl_down_sync(0xffffffffu, best, o);
            int      op = __shfl_down_sync(0xffffffffu, bp, o);
            if (ok > best) { best = ok; bp = op; }
        }
        if (lane == 0) { wk[warp] = best; wp[warp] = bp; }
        __syncthreads();
        if (tid == 0) {
            uint32_t fb = wk[0]; int fp = wp[0];
            #pragma unroll
            for (int w = 1; w < 8; w++)
                if (wk[w] > fb) { fb = wk[w]; fp = wp[w]; }
            g_candi[m * NCAND + r] = 32767 - (int)(fb & 0x7FFFu);
            pool[fp] = 0u;
        }
        __syncthreads();
    }
}

__global__ __launch_bounds__(256) void rescore_select_kernel(const float* __restrict__ fe_w,
                                                             const float* __restrict__ fe_b)
{
    const int m   = blockIdx.x;
    const int tid = threadIdx.x;
    const int lane = tid & 31, warp = tid >> 5;
    __shared__ float uu[EE];
    __shared__ float cv[NCAND];
    __shared__ int   ci[NCAND];

    #pragma unroll
    for (int i = 0; i < 3; i++)
        uu[tid + i * 256] = g_uf[(size_t)m * EE + tid + i * 256];
    __syncthreads();

    const float pn = g_pn[m];
    const float S  = g_S[m];
    for (int c = warp; c < NCAND; c += 8) {
        const int v = g_candi[m * NCAND + c];
        const float4* frow = (const float4*)(fe_w + (size_t)v * EE);
        float acc = 0.f;
        #pragma unroll
        for (int i = 0; i < 6; i++) {
            int idx = lane + i * 32;
            float4 f4 = frow[idx];
            float4 u4 = *(const float4*)&uu[idx * 4];
            acc += f4.x * u4.x + f4.y * u4.y + f4.z * u4.z + f4.w * u4.w;
        }
        #pragma unroll
        for (int o = 16; o > 0; o >>= 1)
            acc += __shfl_down_sync(0xffffffffu, acc, o);
        if (lane == 0) {
            cv[c] = (acc + fe_b[v] * S) / (g_wn[v] * pn);
            ci[c] = v;
        }
    }
    __syncthreads();
    if (tid == 0) {
        float b1 = -INFINITY, b2 = -INFINITY;
        int j1 = 0x7fffffff, j2 = 0x7fffffff;
        #pragma unroll
        for (int c = 0; c < NCAND; c++) {
            float x = cv[c]; int ix = ci[c];
            if (x > b1 || (x == b1 && ix < j1)) { b2 = b1; j2 = j1; b1 = x; j1 = ix; }
            else if (x > b2 || (x == b2 && ix < j2)) { b2 = x; j2 = ix; }
        }
        g_topv[m * 2] = b1;  g_topi[m * 2] = j1;
        g_topv[m * 2 + 1] = b2;  g_topi[m * 2 + 1] = j2;
    }
}

__global__ __launch_bounds__(256) void output_P_kernel(const float* __restrict__ P,
                                                       float* __restrict__ out)
{
    const int m = blockIdx.x;
    const int r = blockIdx.y;
    float* Zrow = out + ((size_t)m * (NPROM + TOPK) + r + TOPK) * DD;
    const float* src = P + ((size_t)m * NPROM + r) * DD;
    const int d = threadIdx.x * 4;
    *(float4*)(Zrow + d) = *(const float4*)(src + d);
    if (r == 0 && threadIdx.x < TOPK) {
        out[(size_t)MM * (NPROM + TOPK) * DD + m * TOPK + threadIdx.x] =
            g_topv[m * TOPK + threadIdx.x];
    }
}

static void* sym_addr(const void* sym)
{
    void* p = nullptr;
    cudaGetSymbolAddress(&p, sym);
    return p;
}

extern "C" void kernel_launch(void* const* d_in, const int* in_sizes, int n_in,
                              void* d_out, int out_size)
{
    const float* P    = (const float*)d_in[0];
    const float* we   = (const float*)d_in[1];
    const float* fe_w = (const float*)d_in[2];
    const float* fe_b = (const float*)d_in[3];
    float* out = (float*)d_out;

    __nv_bfloat16* fwh = (__nv_bfloat16*)sym_addr(g_fwh);
    __nv_bfloat16* fwl = (__nv_bfloat16*)sym_addr(g_fwl);

    static bool attr_done = false;
    if (!attr_done) {
        cudaFuncSetAttribute(mma_u_kernel,
                             cudaFuncAttributeMaxDynamicSharedMemorySize, SMEM_BYTES);
        cudaFuncSetAttribute(mma_G_kernel,
                             cudaFuncAttributeMaxDynamicSharedMemorySize, SMEM_BYTES);
        cudaFuncSetAttribute(mma_H_kernel,
                             cudaFuncAttributeMaxDynamicSharedMemorySize, SMEM_BYTES);
        cudaFuncSetAttribute(mma_scores_kernel,
                             cudaFuncAttributeMaxDynamicSharedMemorySize, SMEM_BYTES);
        cudaFuncSetAttribute(mma_Tsel_kernel,
                             cudaFuncAttributeMaxDynamicSharedMemorySize, SMEM_BYTES);
        attr_done = true;
    }

    split_kernel<<<(VCV * EE / 8 + 255) / 256, 256>>>(fe_w, fwh, fwl, VCV * EE / 8);
    {
        dim3 grid(EE / 32, DD / 32);   // produces weh/wel, weTh/weTl, wsum partials
        trans_split_kernel<<<grid, dim3(32, 8)>>>(we);
    }
    s_pnorm_kernel<<<MM, 256>>>(P);

    {
        dim3 grid(EE / 128, MM / 128);       // 6 x 16
        mma_u_kernel<<<grid, 256, SMEM_BYTES>>>();
    }
    {
        dim3 grid(EE / 128, EE / 128);       // 6 x 6
        mma_G_kernel<<<grid, 256, SMEM_BYTES>>>();
    }
    {
        dim3 grid(EE / 128, VCV / 128);      // 6 x 250
        mma_H_kernel<<<grid, 256, SMEM_BYTES>>>();
    }
    wnorm_fin_kernel<<<VCV / 256, 256>>>(fe_b);
    {
        dim3 grid(VCV / 128, MM / 128);      // 250 x 16
        mma_scores_kernel<<<grid, 256, SMEM_BYTES>>>(fe_b);
    }
    top16_kernel<<<MM, 256>>>();
    rescore_select_kernel<<<MM, 256>>>(fe_w, fe_b);
    {
        dim3 grid(DD / 128, NSEL / 128);     // 8 x 32
        mma_Tsel_kernel<<<grid, 256, SMEM_BYTES>>>(fe_b, out);
    }
    {
        dim3 grid(MM, NPROM);
        output_P_kernel<<<grid, 256>>>(P, out);
    }
    (void)in_sizes; (void)n_in; (void)out_size;
}

// round 17
// speedup vs baseline: 1.0195x; 1.0195x over previous
#include <cuda_runtime.h>
#include <cuda_bf16.h>
#include <math.h>
#include <stdint.h>

#define BATCH 32
#define DIMQ  64
#define NPROM 4
#define DD    1024
#define EE    768
#define VCV   32000
#define MM    (BATCH*DIMQ)   // 2048
#define TOPK  2
#define NCAND 16
#define NSEL  (MM * TOPK)    // 4096
#define EPSV  1e-8f

// -------- scratch --------
__device__ __nv_bfloat16  g_scoresb[(size_t)MM * VCV];
__device__ __nv_bfloat16  g_sh[(size_t)MM * DD];
__device__ __nv_bfloat16  g_sl[(size_t)MM * DD];
__device__ __nv_bfloat16  g_fwh[(size_t)VCV * EE];
__device__ __nv_bfloat16  g_fwl[(size_t)VCV * EE];
__device__ __nv_bfloat16  g_weh[(size_t)DD * EE];
__device__ __nv_bfloat16  g_wel[(size_t)DD * EE];
__device__ __nv_bfloat16  g_weTh[(size_t)EE * DD];
__device__ __nv_bfloat16  g_weTl[(size_t)EE * DD];
__device__ __nv_bfloat16  g_ub[(size_t)MM * EE];     // bf16 u for scores MMA
__device__ float          g_uf[(size_t)MM * EE];     // fp32 u for exact rescore
__device__ __nv_bfloat16  g_Gh[(size_t)EE * EE];     // bf16(we^T we)
__device__ float g_wsump[32 * EE];
__device__ float g_qp[6 * VCV];
__device__ float g_wp[6 * VCV];
__device__ float g_wn[VCV];
__device__ float g_invwn[VCV];
__device__ float g_pn[MM];
__device__ float g_S[MM];
__device__ int   g_candi[MM * NCAND];
__device__ float g_topv[MM * TOPK];
__device__ int   g_topi[MM * TOPK];

// ---------------- helpers ----------------
__device__ __forceinline__ void cp_async16(void* smem, const void* gmem)
{
    uint32_t s = (uint32_t)__cvta_generic_to_shared(smem);
    asm volatile("cp.async.cg.shared.global [%0], [%1], 16;\n" :: "r"(s), "l"(gmem));
}
__device__ __forceinline__ void cp_commit()
{
    asm volatile("cp.async.commit_group;\n" ::);
}
template<int N>
__device__ __forceinline__ void cp_wait()
{
    asm volatile("cp.async.wait_group %0;\n" :: "n"(N));
}

__device__ __forceinline__ void mma16816(float d[4], const uint32_t a[4], const uint32_t b[2])
{
    asm volatile(
        "mma.sync.aligned.m16n8k16.row.col.f32.bf16.bf16.f32 "
        "{%0,%1,%2,%3}, {%4,%5,%6,%7}, {%8,%9}, {%0,%1,%2,%3};"
        : "+f"(d[0]), "+f"(d[1]), "+f"(d[2]), "+f"(d[3])
        : "r"(a[0]), "r"(a[1]), "r"(a[2]), "r"(a[3]), "r"(b[0]), "r"(b[1]));
}

__device__ __forceinline__ void ldsm_x4(uint32_t& r0, uint32_t& r1, uint32_t& r2, uint32_t& r3,
                                        uint32_t addr)
{
    asm volatile("ldmatrix.sync.aligned.m8n8.x4.shared.b16 {%0,%1,%2,%3}, [%4];"
                 : "=r"(r0), "=r"(r1), "=r"(r2), "=r"(r3) : "r"(addr));
}

// 8 floats per thread (fe_w only)
__global__ __launch_bounds__(256) void split_kernel(const float* __restrict__ in,
                                                    __nv_bfloat16* __restrict__ hi,
                                                    __nv_bfloat16* __restrict__ lo,
                                                    int n8)
{
    int i = blockIdx.x * 256 + threadIdx.x;
    if (i >= n8) return;
    #pragma unroll
    for (int q = 0; q < 2; q++) {
        int j = i * 2 + q;
        float4 x = ((const float4*)in)[j];
        __nv_bfloat16 h0 = __float2bfloat16(x.x);
        __nv_bfloat16 h1 = __float2bfloat16(x.y);
        __nv_bfloat16 h2 = __float2bfloat16(x.z);
        __nv_bfloat16 h3 = __float2bfloat16(x.w);
        __nv_bfloat162 hp0{h0, h1}, hp1{h2, h3};
        uint2 hv{*(uint32_t*)&hp0, *(uint32_t*)&hp1};
        ((uint2*)hi)[j] = hv;
        __nv_bfloat162 lp0{__float2bfloat16(x.x - __bfloat162float(h0)),
                           __float2bfloat16(x.y - __bfloat162float(h1))};
        __nv_bfloat162 lp1{__float2bfloat16(x.z - __bfloat162float(h2)),
                           __float2bfloat16(x.w - __bfloat162float(h3))};
        uint2 lv{*(uint32_t*)&lp0, *(uint32_t*)&lp1};
        ((uint2*)lo)[j] = lv;
    }
}

// Fused: we -> weh/wel (row-major split), weTh/weTl (transposed split),
//        wsum partials per 32-row d-block
__global__ void trans_split_kernel(const float* __restrict__ we)
{
    __shared__ float tile[32][33];
    __shared__ float colsum[8][32];
    const int e0 = blockIdx.x * 32;
    const int d0 = blockIdx.y * 32;
    const int tx = threadIdx.x;
    const int ty = threadIdx.y;
    float csum = 0.f;
    #pragma unroll
    for (int i = 0; i < 32; i += 8) {
        float x = we[(size_t)(d0 + ty + i) * EE + e0 + tx];
        tile[ty + i][tx] = x;
        csum += x;
        __nv_bfloat16 h = __float2bfloat16(x);
        size_t ro = (size_t)(d0 + ty + i) * EE + e0 + tx;
        g_weh[ro] = h;
        g_wel[ro] = __float2bfloat16(x - __bfloat162float(h));
    }
    colsum[ty][tx] = csum;
    __syncthreads();
    #pragma unroll
    for (int i = 0; i < 32; i += 8) {
        float x = tile[tx][ty + i];
        size_t o = (size_t)(e0 + ty + i) * DD + d0 + tx;
        __nv_bfloat16 h = __float2bfloat16(x);
        g_weTh[o] = h;
        g_weTl[o] = __float2bfloat16(x - __bfloat162float(h));
    }
    if (ty == 0) {
        float s = 0.f;
        #pragma unroll
        for (int j = 0; j < 8; j++) s += colsum[j][tx];
        g_wsump[(size_t)blockIdx.y * EE + e0 + tx] = s;
    }
}

// ---- MMA tile geometry: 128x128x32, 3-stage pipeline ----
#define BKT     32
#define PADT    8
#define LDST    (BKT + PADT)
#define NSTG    3
#define TILE_ST (128 * LDST)
#define SMEM_BYTES (NSTG * 2 * TILE_ST * 2)   // 61440 B

#define MMA_PREAMBLE \
    extern __shared__ __nv_bfloat16 smem[]; \
    __nv_bfloat16* Asm = smem; \
    __nv_bfloat16* Bsm = smem + NSTG * TILE_ST; \
    const int tid    = threadIdx.x; \
    const int lane   = tid & 31; \
    const int warp   = tid >> 5; \
    const int warp_m = warp >> 2; \
    const int warp_n = warp & 3; \
    const int gid    = lane >> 2; \
    const int tig    = lane & 3; \
    const int c0 = tid * 2, c1 = tid * 2 + 1; \
    const int r0 = c0 >> 2, s0 = (c0 & 3) * 8; \
    const int r1 = c1 >> 2, s1 = (c1 & 3) * 8; \
    const int aRow = warp_m * 64 + (lane & 15); \
    const int aCol = (lane >> 4) * 8; \
    const int bRow = warp_n * 32 + (lane & 7) + ((lane >> 4) << 3); \
    const int bCol = ((lane >> 3) & 1) * 8; \
    const uint32_t sA = (uint32_t)__cvta_generic_to_shared(Asm); \
    const uint32_t sB = (uint32_t)__cvta_generic_to_shared(Bsm); \
    const uint32_t aBase = sA + (uint32_t)(aRow * LDST + aCol) * 2; \
    const uint32_t bBase = sB + (uint32_t)(bRow * LDST + bCol) * 2; \
    float acc[4][4][4]; \
    _Pragma("unroll") \
    for (int mi = 0; mi < 4; mi++) \
        _Pragma("unroll") \
        for (int nj = 0; nj < 4; nj++) \
            _Pragma("unroll") \
            for (int q = 0; q < 4; q++) acc[mi][nj][q] = 0.f;

#define MMA_COMPUTE_TILE(stage) \
    { \
        const uint32_t aB = aBase + (uint32_t)((stage) * TILE_ST) * 2; \
        const uint32_t bB = bBase + (uint32_t)((stage) * TILE_ST) * 2; \
        _Pragma("unroll") \
        for (int ks = 0; ks < 2; ks++) { \
            const uint32_t kOff = (uint32_t)(ks * 16) * 2; \
            uint32_t a[4][4]; \
            uint32_t b[4][2]; \
            _Pragma("unroll") \
            for (int mi = 0; mi < 4; mi++) \
                ldsm_x4(a[mi][0], a[mi][1], a[mi][2], a[mi][3], \
                        aB + (uint32_t)(mi * 16 * LDST) * 2 + kOff); \
            _Pragma("unroll") \
            for (int njp = 0; njp < 2; njp++) \
                ldsm_x4(b[njp*2][0], b[njp*2][1], b[njp*2+1][0], b[njp*2+1][1], \
                        bB + (uint32_t)(njp * 16 * LDST) * 2 + kOff); \
            _Pragma("unroll") \
            for (int mi = 0; mi < 4; mi++) \
                _Pragma("unroll") \
                for (int nj = 0; nj < 4; nj++) \
                    mma16816(acc[mi][nj], a[mi], b[nj]); \
        } \
    }

#define MMA_MAINLOOP(NT, LOADT) \
    LOADT(0, 0); \
    LOADT(1, 1); \
    for (int t = 0; t < (NT); t++) { \
        if (t + 2 < (NT)) { cp_wait<1>(); } else { cp_wait<0>(); } \
        __syncthreads(); \
        if (t + 2 < (NT)) LOADT(t + 2, (t + 2) % NSTG); \
        MMA_COMPUTE_TILE(t % NSTG) \
    }

// =================================================================
// u GEMM: u[m,e] = sum_d s[m,d]*we[d,e] (3-pass split) -> ub bf16 + uf fp32
// =================================================================
__global__ __launch_bounds__(256, 2) void mma_u_kernel()
{
    MMA_PREAMBLE
    const int m0 = blockIdx.y * 128;
    const int n0 = blockIdx.x * 128;

    const int NT = 96;
    auto load_tile = [&](int t, int stage) {
        const int pass = t / 32;
        const int kk   = (t % 32) * BKT;
        const __nv_bfloat16* Ap = (pass < 2) ? g_sh : g_sl;
        const __nv_bfloat16* Bp = (pass == 1) ? g_weTl : g_weTh;
        cp_async16(Asm + stage * TILE_ST + r0 * LDST + s0, Ap + (size_t)(m0 + r0) * DD + kk + s0);
        cp_async16(Asm + stage * TILE_ST + r1 * LDST + s1, Ap + (size_t)(m0 + r1) * DD + kk + s1);
        cp_async16(Bsm + stage * TILE_ST + r0 * LDST + s0, Bp + (size_t)(n0 + r0) * DD + kk + s0);
        cp_async16(Bsm + stage * TILE_ST + r1 * LDST + s1, Bp + (size_t)(n0 + r1) * DD + kk + s1);
        cp_commit();
    };

    MMA_MAINLOOP(NT, load_tile)

    #pragma unroll
    for (int mi = 0; mi < 4; mi++) {
        const int gm0 = m0 + warp_m * 64 + mi * 16 + gid;
        #pragma unroll
        for (int nj = 0; nj < 4; nj++) {
            const int gn = n0 + warp_n * 32 + nj * 8 + tig * 2;
            __nv_bfloat16* o0 = g_ub + (size_t)gm0 * EE + gn;
            __nv_bfloat16* o1 = g_ub + (size_t)(gm0 + 8) * EE + gn;
            o0[0] = __float2bfloat16(acc[mi][nj][0]);
            o0[1] = __float2bfloat16(acc[mi][nj][1]);
            o1[0] = __float2bfloat16(acc[mi][nj][2]);
            o1[1] = __float2bfloat16(acc[mi][nj][3]);
            float* f0 = g_uf + (size_t)gm0 * EE + gn;
            float* f1 = g_uf + (size_t)(gm0 + 8) * EE + gn;
            f0[0] = acc[mi][nj][0];  f0[1] = acc[mi][nj][1];
            f1[0] = acc[mi][nj][2];  f1[1] = acc[mi][nj][3];
        }
    }
}

// =================================================================
// G GEMM: G = we^T we (3-pass split) -> Gh bf16
// =================================================================
__global__ __launch_bounds__(256, 2) void mma_G_kernel()
{
    MMA_PREAMBLE
    const int m0 = blockIdx.y * 128;
    const int n0 = blockIdx.x * 128;

    const int NT = 96;
    auto load_tile = [&](int t, int stage) {
        const int pass = t / 32;
        const int kk   = (t % 32) * BKT;
        const __nv_bfloat16* Ap = (pass < 2) ? g_weTh : g_weTl;
        const __nv_bfloat16* Bp = (pass == 1) ? g_weTl : g_weTh;
        cp_async16(Asm + stage * TILE_ST + r0 * LDST + s0, Ap + (size_t)(m0 + r0) * DD + kk + s0);
        cp_async16(Asm + stage * TILE_ST + r1 * LDST + s1, Ap + (size_t)(m0 + r1) * DD + kk + s1);
        cp_async16(Bsm + stage * TILE_ST + r0 * LDST + s0, Bp + (size_t)(n0 + r0) * DD + kk + s0);
        cp_async16(Bsm + stage * TILE_ST + r1 * LDST + s1, Bp + (size_t)(n0 + r1) * DD + kk + s1);
        cp_commit();
    };

    MMA_MAINLOOP(NT, load_tile)

    #pragma unroll
    for (int mi = 0; mi < 4; mi++) {
        const int gm0 = m0 + warp_m * 64 + mi * 16 + gid;
        #pragma unroll
        for (int nj = 0; nj < 4; nj++) {
            const int gn = n0 + warp_n * 32 + nj * 8 + tig * 2;
            g_Gh[(size_t)gm0 * EE + gn]       = __float2bfloat16(acc[mi][nj][0]);
            g_Gh[(size_t)gm0 * EE + gn + 1]   = __float2bfloat16(acc[mi][nj][1]);
            g_Gh[(size_t)(gm0+8) * EE + gn]   = __float2bfloat16(acc[mi][nj][2]);
            g_Gh[(size_t)(gm0+8) * EE + gn+1] = __float2bfloat16(acc[mi][nj][3]);
        }
    }
}

// =================================================================
// H GEMM (1-pass) + fused q/w partials
// =================================================================
__global__ __launch_bounds__(256, 2) void mma_H_kernel()
{
    MMA_PREAMBLE
    const int m0 = blockIdx.y * 128;   // v
    const int n0 = blockIdx.x * 128;   // e

    const int NT = EE / BKT;  // 24
    auto load_tile = [&](int t, int stage) {
        const int kk = t * BKT;
        cp_async16(Asm + stage * TILE_ST + r0 * LDST + s0, g_fwh + (size_t)(m0 + r0) * EE + kk + s0);
        cp_async16(Asm + stage * TILE_ST + r1 * LDST + s1, g_fwh + (size_t)(m0 + r1) * EE + kk + s1);
        cp_async16(Bsm + stage * TILE_ST + r0 * LDST + s0, g_Gh + (size_t)(n0 + r0) * EE + kk + s0);
        cp_async16(Bsm + stage * TILE_ST + r1 * LDST + s1, g_Gh + (size_t)(n0 + r1) * EE + kk + s1);
        cp_commit();
    };

    MMA_MAINLOOP(NT, load_tile)

    __syncthreads();
    float* rowq = (float*)smem;
    float* roww = (float*)smem + 128;
    float* wsm  = (float*)smem + 256;
    if (tid < 128) { rowq[tid] = 0.f; roww[tid] = 0.f; }
    if (tid < 128) {
        float s = 0.f;
        #pragma unroll
        for (int i = 0; i < 32; i++)
            s += g_wsump[(size_t)i * EE + n0 + tid];
        wsm[tid] = s;
    }
    __syncthreads();

    #pragma unroll
    for (int mi = 0; mi < 4; mi++) {
        const int lr0 = warp_m * 64 + mi * 16 + gid;
        const int gm0 = m0 + lr0;
        float q0 = 0.f, q1 = 0.f, w0 = 0.f, w1 = 0.f;
        #pragma unroll
        for (int nj = 0; nj < 4; nj++) {
            const int gn = n0 + warp_n * 32 + nj * 8 + tig * 2;
            const int ln = gn - n0;
            __nv_bfloat162 h0 = *(const __nv_bfloat162*)(g_fwh + (size_t)gm0 * EE + gn);
            __nv_bfloat162 l0 = *(const __nv_bfloat162*)(g_fwl + (size_t)gm0 * EE + gn);
            __nv_bfloat162 h1 = *(const __nv_bfloat162*)(g_fwh + (size_t)(gm0+8) * EE + gn);
            __nv_bfloat162 l1 = *(const __nv_bfloat162*)(g_fwl + (size_t)(gm0+8) * EE + gn);
            float fh00 = __bfloat162float(h0.x), fh01 = __bfloat162float(h0.y);
            float fl00 = __bfloat162float(l0.x), fl01 = __bfloat162float(l0.y);
            float fh10 = __bfloat162float(h1.x), fh11 = __bfloat162float(h1.y);
            float fl10 = __bfloat162float(l1.x), fl11 = __bfloat162float(l1.y);
            q0 += acc[mi][nj][0] * (fh00 + 2.f * fl00) + acc[mi][nj][1] * (fh01 + 2.f * fl01);
            q1 += acc[mi][nj][2] * (fh10 + 2.f * fl10) + acc[mi][nj][3] * (fh11 + 2.f * fl11);
            w0 += (fh00 + fl00) * wsm[ln] + (fh01 + fl01) * wsm[ln + 1];
            w1 += (fh10 + fl10) * wsm[ln] + (fh11 + fl11) * wsm[ln + 1];
        }
        atomicAdd(&rowq[lr0], q0);
        atomicAdd(&rowq[lr0 + 8], q1);
        atomicAdd(&roww[lr0], w0);
        atomicAdd(&roww[lr0 + 8], w1);
    }
    __syncthreads();
    if (tid < 128) {
        g_qp[(size_t)blockIdx.x * VCV + m0 + tid] = rowq[tid];
        g_wp[(size_t)blockIdx.x * VCV + m0 + tid] = roww[tid];
    }
}

__global__ __launch_bounds__(256) void wnorm_fin_kernel(const float* __restrict__ fe_b)
{
    const int v = blockIdx.x * 256 + threadIdx.x;
    float q = 0.f, w = 0.f;
    #pragma unroll
    for (int i = 0; i < 6; i++) {
        q += g_qp[(size_t)i * VCV + v];
        w += g_wp[(size_t)i * VCV + v];
    }
    const float b = fe_b[v];
    float nsq = fmaxf(q + 2.f * b * w + (float)DD * b * b, 0.f);
    float wn = fmaxf(2.0f * sqrtf(nsq), EPSV);
    g_wn[v] = wn;
    g_invwn[v] = 1.0f / wn;
}

// =================================================================
// scores[m,v] = (ub[m].fwh[v] + b[v]*S[m]) * invwn[v], stored bf16
// =================================================================
__global__ __launch_bounds__(256, 2) void mma_scores_kernel(const float* __restrict__ fe_b)
{
    MMA_PREAMBLE
    const int m0 = blockIdx.y * 128;
    const int n0 = blockIdx.x * 128;

    const int NT = EE / BKT;  // 24
    auto load_tile = [&](int t, int stage) {
        const int kk = t * BKT;
        cp_async16(Asm + stage * TILE_ST + r0 * LDST + s0, g_ub + (size_t)(m0 + r0) * EE + kk + s0);
        cp_async16(Asm + stage * TILE_ST + r1 * LDST + s1, g_ub + (size_t)(m0 + r1) * EE + kk + s1);
        cp_async16(Bsm + stage * TILE_ST + r0 * LDST + s0, g_fwh + (size_t)(n0 + r0) * EE + kk + s0);
        cp_async16(Bsm + stage * TILE_ST + r1 * LDST + s1, g_fwh + (size_t)(n0 + r1) * EE + kk + s1);
        cp_commit();
    };

    MMA_MAINLOOP(NT, load_tile)

    #pragma unroll
    for (int mi = 0; mi < 4; mi++) {
        const int gm0 = m0 + warp_m * 64 + mi * 16 + gid;
        const float S0 = g_S[gm0];
        const float S1 = g_S[gm0 + 8];
        #pragma unroll
        for (int nj = 0; nj < 4; nj++) {
            const int gn = n0 + warp_n * 32 + nj * 8 + tig * 2;
            const float iw0 = g_invwn[gn],  iw1 = g_invwn[gn + 1];
            const float bb0 = fe_b[gn],     bb1 = fe_b[gn + 1];
            __nv_bfloat162 p0{__float2bfloat16((acc[mi][nj][0] + bb0 * S0) * iw0),
                              __float2bfloat16((acc[mi][nj][1] + bb1 * S0) * iw1)};
            __nv_bfloat162 p1{__float2bfloat16((acc[mi][nj][2] + bb0 * S1) * iw0),
                              __float2bfloat16((acc[mi][nj][3] + bb1 * S1) * iw1)};
            *(__nv_bfloat162*)(g_scoresb + (size_t)gm0 * VCV + gn) = p0;
            *(__nv_bfloat162*)(g_scoresb + (size_t)(gm0 + 8) * VCV + gn) = p1;
        }
    }
}

// =================================================================
// Tsel GEMM: Z e_k rows (gathered, 3-pass split, writes into out)
// =================================================================
__global__ __launch_bounds__(256, 2) void mma_Tsel_kernel(const float* __restrict__ fe_b,
                                                          float* __restrict__ out)
{
    MMA_PREAMBLE
    const int m0 = blockIdx.y * 128;
    const int n0 = blockIdx.x * 128;

    const int sel0 = g_topi[m0 + r0];
    const int sel1 = g_topi[m0 + r1];

    const int NT = 72;
    auto load_tile = [&](int t, int stage) {
        const int pass = t / 24;
        const int kk   = (t % 24) * BKT;
        const __nv_bfloat16* Ap = (pass < 2) ? g_fwh : g_fwl;
        const __nv_bfloat16* Bp = (pass == 1) ? g_wel : g_weh;
        cp_async16(Asm + stage * TILE_ST + r0 * LDST + s0, Ap + (size_t)sel0 * EE + kk + s0);
        cp_async16(Asm + stage * TILE_ST + r1 * LDST + s1, Ap + (size_t)sel1 * EE + kk + s1);
        cp_async16(Bsm + stage * TILE_ST + r0 * LDST + s0, Bp + (size_t)(n0 + r0) * EE + kk + s0);
        cp_async16(Bsm + stage * TILE_ST + r1 * LDST + s1, Bp + (size_t)(n0 + r1) * EE + kk + s1);
        cp_commit();
    };

    MMA_MAINLOOP(NT, load_tile)

    #pragma unroll
    for (int mi = 0; mi < 4; mi++) {
        const int gm0 = m0 + warp_m * 64 + mi * 16 + gid;
        const int gm1 = gm0 + 8;
        const float b0 = fe_b[g_topi[gm0]];
        const float b1 = fe_b[g_topi[gm1]];
        float* dst0 = out + ((size_t)(gm0 >> 1) * (NPROM + TOPK) + (gm0 & 1)) * DD;
        float* dst1 = out + ((size_t)(gm1 >> 1) * (NPROM + TOPK) + (gm1 & 1)) * DD;
        #pragma unroll
        for (int nj = 0; nj < 4; nj++) {
            const int gn = n0 + warp_n * 32 + nj * 8 + tig * 2;
            dst0[gn]     = acc[mi][nj][0] + b0;
            dst0[gn + 1] = acc[mi][nj][1] + b0;
            dst1[gn]     = acc[mi][nj][2] + b1;
            dst1[gn + 1] = acc[mi][nj][3] + b1;
        }
    }
}

// ---------------- small kernels ----------------
__global__ __launch_bounds__(256) void s_pnorm_kernel(const float* __restrict__ P)
{
    const int m = blockIdx.x;
    const float* base = P + (size_t)m * NPROM * DD;
    float ss = 0.f, rs = 0.f;
    #pragma unroll
    for (int i = 0; i < 4; i++) {
        int d = threadIdx.x + i * 256;
        float a = base[d];
        float b = base[DD + d];
        float c = base[2 * DD + d];
        float e = base[3 * DD + d];
        float sum = (a + b) + (c + e);
        __nv_bfloat16 h = __float2bfloat16(sum);
        g_sh[(size_t)m * DD + d] = h;
        g_sl[(size_t)m * DD + d] = __float2bfloat16(sum - __bfloat162float(h));
        ss += a * a + b * b + c * c + e * e;
        rs += sum;
    }
    __shared__ float red[256];
    __shared__ float red2[256];
    red[threadIdx.x] = ss;
    red2[threadIdx.x] = rs;
    __syncthreads();
    for (int o = 128; o > 0; o >>= 1) {
        if (threadIdx.x < o) {
            red[threadIdx.x]  += red[threadIdx.x + o];
            red2[threadIdx.x] += red2[threadIdx.x + o];
        }
        __syncthreads();
    }
    if (threadIdx.x == 0) {
        g_pn[m] = fmaxf(sqrtf(red[0]), EPSV);
        g_S[m]  = red2[0];
    }
}

__device__ __forceinline__ uint32_t ord_bf16(uint32_t u16bits)
{
    return (u16bits & 0x8000u) ? (~u16bits & 0xFFFFu) : (u16bits | 0x8000u);
}

__global__ __launch_bounds__(256) void top16_kernel()
{
    const int m   = blockIdx.x;
    const int tid = threadIdx.x;
    const int lane = tid & 31, warp = tid >> 5;
    const uint4* row = (const uint4*)(g_scoresb + (size_t)m * VCV);

    uint32_t loc[4] = {0u, 0u, 0u, 0u};

    for (int i = tid; i < VCV / 8; i += 256) {
        uint4 x = row[i];
        const int base = i * 8;
        uint32_t ws[4] = {x.x, x.y, x.z, x.w};
        #pragma unroll
        for (int p = 0; p < 4; p++) {
            #pragma unroll
            for (int h = 0; h < 2; h++) {
                uint32_t bits = (h == 0) ? (ws[p] & 0xFFFFu) : (ws[p] >> 16);
                int idx = base + p * 2 + h;
                uint32_t key = (ord_bf16(bits) << 15) | (uint32_t)(32767 - idx);
                if (key > loc[3]) {
                    bool placed = false;
                    #pragma unroll
                    for (int j = 3; j >= 1; --j) {
                        if (!placed) {
                            if (key > loc[j - 1]) loc[j] = loc[j - 1];
                            else { loc[j] = key; placed = true; }
                        }
                    }
                    if (!placed) loc[0] = key;
                }
            }
        }
    }

    __shared__ uint32_t pool[1024];
    __shared__ uint32_t wk[8];
    __shared__ int      wp[8];
    #pragma unroll
    for (int j = 0; j < 4; j++) pool[tid * 4 + j] = loc[j];
    __syncthreads();

    for (int r = 0; r < NCAND; r++) {
        uint32_t best = pool[tid * 4];
        int bp = tid * 4;
        #pragma unroll
        for (int j = 1; j < 4; j++) {
            uint32_t k = pool[tid * 4 + j];
            if (k > best) { best = k; bp = tid * 4 + j; }
        }
        #pragma unroll
        for (int o = 16; o > 0; o >>= 1) {
            uint32_t ok = __shfl_down_sync(0xffffffffu, best, o);
            int      op = __shfl_down_sync(0xffffffffu, bp, o);
            if (ok > best) { best = ok; bp = op; }
        }
        if (lane == 0) { wk[warp] = best; wp[warp] = bp; }
        __syncthreads();
        if (tid == 0) {
            uint32_t fb = wk[0]; int fp = wp[0];
            #pragma unroll
            for (int w = 1; w < 8; w++)
                if (wk[w] > fb) { fb = wk[w]; fp = wp[w]; }
            g_candi[m * NCAND + r] = 32767 - (int)(fb & 0x7FFFu);
            pool[fp] = 0u;
        }
        __syncthreads();
    }
}

__global__ __launch_bounds__(256) void rescore_select_kernel(const float* __restrict__ fe_w,
                                                             const float* __restrict__ fe_b)
{
    const int m   = blockIdx.x;
    const int tid = threadIdx.x;
    const int lane = tid & 31, warp = tid >> 5;
    __shared__ float uu[EE];
    __shared__ float cv[NCAND];
    __shared__ int   ci[NCAND];

    #pragma unroll
    for (int i = 0; i < 3; i++)
        uu[tid + i * 256] = g_uf[(size_t)m * EE + tid + i * 256];
    __syncthreads();

    const float pn = g_pn[m];
    const float S  = g_S[m];
    for (int c = warp; c < NCAND; c += 8) {
        const int v = g_candi[m * NCAND + c];
        const float4* frow = (const float4*)(fe_w + (size_t)v * EE);
        float acc = 0.f;
        #pragma unroll
        for (int i = 0; i < 6; i++) {
            int idx = lane + i * 32;
            float4 f4 = frow[idx];
            float4 u4 = *(const float4*)&uu[idx * 4];
            acc += f4.x * u4.x + f4.y * u4.y + f4.z * u4.z + f4.w * u4.w;
        }
        #pragma unroll
        for (int o = 16; o > 0; o >>= 1)
            acc += __shfl_down_sync(0xffffffffu, acc, o);
        if (lane == 0) {
            cv[c] = (acc + fe_b[v] * S) / (g_wn[v] * pn);
            ci[c] = v;
        }
    }
    __syncthreads();
    if (tid == 0) {
        float b1 = -INFINITY, b2 = -INFINITY;
        int j1 = 0x7fffffff, j2 = 0x7fffffff;
        #pragma unroll
        for (int c = 0; c < NCAND; c++) {
            float x = cv[c]; int ix = ci[c];
            if (x > b1 || (x == b1 && ix < j1)) { b2 = b1; j2 = j1; b1 = x; j1 = ix; }
            else if (x > b2 || (x == b2 && ix < j2)) { b2 = x; j2 = ix; }
        }
        g_topv[m * 2] = b1;  g_topi[m * 2] = j1;
        g_topv[m * 2 + 1] = b2;  g_topi[m * 2 + 1] = j2;
    }
}

__global__ __launch_bounds__(256) void output_P_kernel(const float* __restrict__ P,
                                                       float* __restrict__ out)
{
    const int m = blockIdx.x;
    const int r = blockIdx.y;
    float* Zrow = out + ((size_t)m * (NPROM + TOPK) + r + TOPK) * DD;
    const float* src = P + ((size_t)m * NPROM + r) * DD;
    const int d = threadIdx.x * 4;
    *(float4*)(Zrow + d) = *(const float4*)(src + d);
    if (r == 0 && threadIdx.x < TOPK) {
        out[(size_t)MM * (NPROM + TOPK) * DD + m * TOPK + threadIdx.x] =
            g_topv[m * TOPK + threadIdx.x];
    }
}

static void* sym_addr(const void* sym)
{
    void* p = nullptr;
    cudaGetSymbolAddress(&p, sym);
    return p;
}

extern "C" void kernel_launch(void* const* d_in, const int* in_sizes, int n_in,
                              void* d_out, int out_size)
{
    const float* P    = (const float*)d_in[0];
    const float* we   = (const float*)d_in[1];
    const float* fe_w = (const float*)d_in[2];
    const float* fe_b = (const float*)d_in[3];
    float* out = (float*)d_out;

    __nv_bfloat16* fwh = (__nv_bfloat16*)sym_addr(g_fwh);
    __nv_bfloat16* fwl = (__nv_bfloat16*)sym_addr(g_fwl);

    static bool attr_done = false;
    if (!attr_done) {
        cudaFuncSetAttribute(mma_u_kernel,
                             cudaFuncAttributeMaxDynamicSharedMemorySize, SMEM_BYTES);
        cudaFuncSetAttribute(mma_G_kernel,
                             cudaFuncAttributeMaxDynamicSharedMemorySize, SMEM_BYTES);
        cudaFuncSetAttribute(mma_H_kernel,
                             cudaFuncAttributeMaxDynamicSharedMemorySize, SMEM_BYTES);
        cudaFuncSetAttribute(mma_scores_kernel,
                             cudaFuncAttributeMaxDynamicSharedMemorySize, SMEM_BYTES);
        cudaFuncSetAttribute(mma_Tsel_kernel,
                             cudaFuncAttributeMaxDynamicSharedMemorySize, SMEM_BYTES);
        attr_done = true;
    }

    split_kernel<<<(VCV * EE / 8 + 255) / 256, 256>>>(fe_w, fwh, fwl, VCV * EE / 8);
    {
        dim3 grid(EE / 32, DD / 32);   // weh/wel + weTh/weTl + wsum partials
        trans_split_kernel<<<grid, dim3(32, 8)>>>(we);
    }
    s_pnorm_kernel<<<MM, 256>>>(P);

    {
        dim3 grid(EE / 128, MM / 128);       // 6 x 16
        mma_u_kernel<<<grid, 256, SMEM_BYTES>>>();
    }
    {
        dim3 grid(EE / 128, EE / 128);       // 6 x 6
        mma_G_kernel<<<grid, 256, SMEM_BYTES>>>();
    }
    {
        dim3 grid(EE / 128, VCV / 128);      // 6 x 250
        mma_H_kernel<<<grid, 256, SMEM_BYTES>>>();
    }
    wnorm_fin_kernel<<<VCV / 256, 256>>>(fe_b);
    {
        dim3 grid(VCV / 128, MM / 128);      // 250 x 16
        mma_scores_kernel<<<grid, 256, SMEM_BYTES>>>(fe_b);
    }
    top16_kernel<<<MM, 256>>>();
    rescore_select_kernel<<<MM, 256>>>(fe_w, fe_b);
    {
        dim3 grid(DD / 128, NSEL / 128);     // 8 x 32
        mma_Tsel_kernel<<<grid, 256, SMEM_BYTES>>>(fe_b, out);
    }
    {
        dim3 grid(MM, NPROM);
        output_P_kernel<<<grid, 256>>>(P, out);
    }
    (void)in_sizes; (void)n_in; (void)out_size;
}